// round 9
// baseline (speedup 1.0000x reference)
#include <cuda_runtime.h>
#include <cuda_bf16.h>
#include <cstdint>

#define L_TOK 4096
#define DIMC 576
#define QKVD 1728
#define NHEADS 8
#define DH 72
#define OUTC 128

// Scratch (allocation-free: __device__ globals)
__device__ float g_x[L_TOK * DIMC];      // unfold output  [L,576]
__device__ float g_qkv[L_TOK * QKVD];    // q fp32 | k tf32-bits (d-interleaved) | (v unused)
__device__ float g_vT[DIMC * L_TOK];     // v tf32-bits, transposed [d][token], token-interleaved
__device__ float g_attn[L_TOK * DIMC];   // attention out  [L,576]
__device__ float g_x2[L_TOK * DIMC];     // attn+resid     [L,576]

// ---------------------------------------------------------------------------
// helpers
// ---------------------------------------------------------------------------
__device__ __forceinline__ uint32_t f2tf32(float x) {
    uint32_t r;
    asm("cvt.rna.tf32.f32 %0, %1;" : "=r"(r) : "f"(x));
    return r;
}

__device__ __forceinline__ void mma_tf32(float d[4],
                                         const uint32_t a[4],
                                         uint32_t b0, uint32_t b1) {
    asm volatile(
        "mma.sync.aligned.m16n8k8.row.col.f32.tf32.tf32.f32 "
        "{%0,%1,%2,%3}, {%4,%5,%6,%7}, {%8,%9}, {%0,%1,%2,%3};\n"
        : "+f"(d[0]), "+f"(d[1]), "+f"(d[2]), "+f"(d[3])
        : "r"(a[0]), "r"(a[1]), "r"(a[2]), "r"(a[3]), "r"(b0), "r"(b1));
}

__device__ __forceinline__ void cp16(uint32_t smem_addr, const void* gptr) {
    asm volatile("cp.async.cg.shared.global [%0], [%1], 16;\n"
                 :: "r"(smem_addr), "l"(gptr));
}
#define CP_COMMIT() asm volatile("cp.async.commit_group;\n" ::: "memory")
#define CP_WAIT0()  asm volatile("cp.async.wait_group 0;\n" ::: "memory")

// pair-interleave: memory position of index j within an 8-group, such that
// positions (2i, 2i+1) hold indices (i, i+4)  ->  one LDS.64 = (b0, b1)
__device__ __forceinline__ int kvpos(int j) { return 2 * (j & 3) + (j >> 2); }

// ---------------------------------------------------------------------------
// Unfold 3x3 stride2 pad1
// ---------------------------------------------------------------------------
__global__ void unfold_kernel(const float* __restrict__ fea, float* __restrict__ x) {
    int idx = blockIdx.x * blockDim.x + threadIdx.x;
    if (idx >= L_TOK * DIMC) return;
    int l = idx / DIMC, d = idx - l * DIMC;
    int c = d / 9, r = d - c * 9;
    int ki = r / 3, kj = r - ki * 3;
    int ho = l >> 6, wo = l & 63;
    int h = 2 * ho + ki - 1;
    int w = 2 * wo + kj - 1;
    float v = 0.f;
    if (h >= 0 && h < 128 && w >= 0 && w < 128)
        v = fea[c * 16384 + h * 128 + w];
    x[idx] = v;
}

// ---------------------------------------------------------------------------
// Pipelined tf32 GEMM. MODE 0: +bias; MODE 1: +bias+resid.
// CVTKV (mode 0 qkv only): K columns stored tf32-rounded + d-interleaved;
// V columns stored tf32-rounded, transposed into vT, token-interleaved.
// ---------------------------------------------------------------------------
#define AST 20
#define BST 72

template <int MODE, bool CVTKV>
__global__ void __launch_bounds__(256) tf32_gemm_pipe(
    const float* __restrict__ A, const float* __restrict__ B,
    const float* __restrict__ bias, const float* __restrict__ resid,
    float* __restrict__ C, float* __restrict__ vT, int M, int N, int K)
{
    __shared__ __align__(16) float As[2][128 * AST];
    __shared__ __align__(16) float Bs[2][16 * BST];

    const int tid  = threadIdx.x;
    const int lane = tid & 31;
    const int warp = tid >> 5;
    const int g = lane >> 2;
    const int t = lane & 3;
    const int wm = (warp >> 1) * 32;
    const int wn = (warp & 1) * 32;
    const int bm = blockIdx.y * 128;
    const int bn = blockIdx.x * 64;

    const int a_row0 = (tid * 2) >> 2;
    const int a_c0   = (tid * 2) & 3;
    const int a_row1 = (tid * 2 + 1) >> 2;
    const int a_c1   = (tid * 2 + 1) & 3;
    const int b_row  = tid >> 4;
    const int b_c    = tid & 15;

    auto stage = [&](int k0, int buf) {
        cp16(__cvta_generic_to_shared(&As[buf][a_row0 * AST + a_c0 * 4]),
             A + (long)(bm + a_row0) * K + k0 + a_c0 * 4);
        cp16(__cvta_generic_to_shared(&As[buf][a_row1 * AST + a_c1 * 4]),
             A + (long)(bm + a_row1) * K + k0 + a_c1 * 4);
        cp16(__cvta_generic_to_shared(&Bs[buf][b_row * BST + b_c * 4]),
             B + (long)(k0 + b_row) * N + bn + b_c * 4);
    };

    float acc[2][4][4];
#pragma unroll
    for (int i = 0; i < 2; i++)
#pragma unroll
        for (int j = 0; j < 4; j++)
#pragma unroll
            for (int f = 0; f < 4; f++) acc[i][j][f] = 0.f;

    const int ns = K / 16;
    stage(0, 0);
    CP_COMMIT();

    for (int kt = 0; kt < ns; kt++) {
        CP_WAIT0();
        __syncthreads();
        if (kt + 1 < ns) {
            stage((kt + 1) * 16, (kt + 1) & 1);
            CP_COMMIT();
        }
        const float* Ab = As[kt & 1];
        const float* Bb = Bs[kt & 1];
#pragma unroll
        for (int ks = 0; ks < 2; ks++) {
            uint32_t af[2][4];
#pragma unroll
            for (int i = 0; i < 2; i++) {
                int mb = wm + i * 16;
                af[i][0] = f2tf32(Ab[(mb + g)     * AST + ks * 8 + t]);
                af[i][1] = f2tf32(Ab[(mb + g + 8) * AST + ks * 8 + t]);
                af[i][2] = f2tf32(Ab[(mb + g)     * AST + ks * 8 + t + 4]);
                af[i][3] = f2tf32(Ab[(mb + g + 8) * AST + ks * 8 + t + 4]);
            }
#pragma unroll
            for (int j = 0; j < 4; j++) {
                uint32_t b0 = f2tf32(Bb[(ks * 8 + t)     * BST + wn + j * 8 + g]);
                uint32_t b1 = f2tf32(Bb[(ks * 8 + t + 4) * BST + wn + j * 8 + g]);
                mma_tf32(acc[0][j], af[0], b0, b1);
                mma_tf32(acc[1][j], af[1], b0, b1);
            }
        }
    }

    // epilogue — section is block-uniform (bn granularity 64 divides 576)
    const int sec = (!CVTKV) ? 0 : (bn >= 2 * DIMC ? 2 : (bn >= DIMC ? 1 : 0));
#pragma unroll
    for (int i = 0; i < 2; i++) {
#pragma unroll
        for (int j = 0; j < 4; j++) {
            int m0 = bm + wm + i * 16 + g;
            int m1 = m0 + 8;
            int n  = bn + wn + j * 8 + 2 * t;
            float2 bb = *(const float2*)(bias + n);
            if (MODE == 0) {
                float v00 = acc[i][j][0] + bb.x, v01 = acc[i][j][1] + bb.y;
                float v10 = acc[i][j][2] + bb.x, v11 = acc[i][j][3] + bb.y;
                if (sec == 0) {
                    *(float2*)(C + (long)m0 * N + n) = make_float2(v00, v01);
                    *(float2*)(C + (long)m1 * N + n) = make_float2(v10, v11);
                } else if (sec == 1) {
                    // K: tf32 bits, d-interleaved within 8-group
                    uint32_t* Cu = (uint32_t*)C;
                    int base8 = bn + wn + j * 8;
                    int n0 = base8 + kvpos(2 * t);
                    int n1 = base8 + kvpos(2 * t + 1);
                    Cu[(long)m0 * N + n0] = f2tf32(v00);
                    Cu[(long)m0 * N + n1] = f2tf32(v01);
                    Cu[(long)m1 * N + n0] = f2tf32(v10);
                    Cu[(long)m1 * N + n1] = f2tf32(v11);
                } else {
                    // V: tf32 bits, transposed [d][token], token-interleaved
                    uint32_t* Vu = (uint32_t*)vT;
                    int d0 = n - 2 * DIMC;            // even
                    int mp0 = (m0 & ~7) + kvpos(g);
                    int mp1 = mp0 + 8;
                    Vu[(long)d0 * L_TOK + mp0]       = f2tf32(v00);
                    Vu[(long)(d0 + 1) * L_TOK + mp0] = f2tf32(v01);
                    Vu[(long)d0 * L_TOK + mp1]       = f2tf32(v10);
                    Vu[(long)(d0 + 1) * L_TOK + mp1] = f2tf32(v11);
                }
            } else {
                float2 r0 = *(const float2*)(resid + (long)m0 * N + n);
                float2 r1 = *(const float2*)(resid + (long)m1 * N + n);
                *(float2*)(C + (long)m0 * N + n) =
                    make_float2(acc[i][j][0] + bb.x + r0.x, acc[i][j][1] + bb.y + r0.y);
                *(float2*)(C + (long)m1 * N + n) =
                    make_float2(acc[i][j][2] + bb.x + r1.x, acc[i][j][3] + bb.y + r1.y);
            }
        }
    }
}

// ---------------------------------------------------------------------------
// Final GEMM (TRANSB, silu, transposed store) — small, R3 style
// ---------------------------------------------------------------------------
__global__ void __launch_bounds__(256) tf32_gemm_final(
    const float* __restrict__ A, const float* __restrict__ B,
    float* __restrict__ C, int M, int N, int K)
{
    __shared__ __align__(16) uint32_t As[128 * AST];
    __shared__ __align__(16) uint32_t Bs[16 * BST];

    const int tid  = threadIdx.x;
    const int lane = tid & 31;
    const int warp = tid >> 5;
    const int g = lane >> 2;
    const int t = lane & 3;
    const int wm = (warp >> 1) * 32;
    const int wn = (warp & 1) * 32;
    const int bm = blockIdx.y * 128;
    const int bn = blockIdx.x * 64;

    const int a_m = tid >> 1;
    const int a_k = (tid & 1) * 8;
    const int b_n = tid >> 2;
    const int b_k = (tid & 3) * 4;

    float acc[2][4][4];
#pragma unroll
    for (int i = 0; i < 2; i++)
#pragma unroll
        for (int j = 0; j < 4; j++)
#pragma unroll
            for (int f = 0; f < 4; f++) acc[i][j][f] = 0.f;

    for (int k0 = 0; k0 < K; k0 += 16) {
        {
            const float* Ap = A + (long)(bm + a_m) * K + k0 + a_k;
            float4 v0 = *(const float4*)(Ap);
            float4 v1 = *(const float4*)(Ap + 4);
            *(uint4*)&As[a_m * AST + a_k] =
                make_uint4(f2tf32(v0.x), f2tf32(v0.y), f2tf32(v0.z), f2tf32(v0.w));
            *(uint4*)&As[a_m * AST + a_k + 4] =
                make_uint4(f2tf32(v1.x), f2tf32(v1.y), f2tf32(v1.z), f2tf32(v1.w));
        }
        {
            float4 bv = *(const float4*)(B + (long)(bn + b_n) * K + k0 + b_k);
            Bs[(b_k + 0) * BST + b_n] = f2tf32(bv.x);
            Bs[(b_k + 1) * BST + b_n] = f2tf32(bv.y);
            Bs[(b_k + 2) * BST + b_n] = f2tf32(bv.z);
            Bs[(b_k + 3) * BST + b_n] = f2tf32(bv.w);
        }
        __syncthreads();

#pragma unroll
        for (int ks = 0; ks < 2; ks++) {
            uint32_t af[2][4];
#pragma unroll
            for (int i = 0; i < 2; i++) {
                int mb = wm + i * 16;
                af[i][0] = As[(mb + g)     * AST + ks * 8 + t];
                af[i][1] = As[(mb + g + 8) * AST + ks * 8 + t];
                af[i][2] = As[(mb + g)     * AST + ks * 8 + t + 4];
                af[i][3] = As[(mb + g + 8) * AST + ks * 8 + t + 4];
            }
#pragma unroll
            for (int j = 0; j < 4; j++) {
                uint32_t b0 = Bs[(ks * 8 + t)     * BST + wn + j * 8 + g];
                uint32_t b1 = Bs[(ks * 8 + t + 4) * BST + wn + j * 8 + g];
                mma_tf32(acc[0][j], af[0], b0, b1);
                mma_tf32(acc[1][j], af[1], b0, b1);
            }
        }
        __syncthreads();
    }

#pragma unroll
    for (int i = 0; i < 2; i++) {
#pragma unroll
        for (int j = 0; j < 4; j++) {
            int m0 = bm + wm + i * 16 + g;
            int m1 = m0 + 8;
            int n  = bn + wn + j * 8 + 2 * t;
            float v0 = acc[i][j][0], v1 = acc[i][j][1];
            float v2 = acc[i][j][2], v3 = acc[i][j][3];
            C[(long)n * M + m0]       = v0 / (1.f + __expf(-v0));
            C[(long)(n + 1) * M + m0] = v1 / (1.f + __expf(-v1));
            C[(long)n * M + m1]       = v2 / (1.f + __expf(-v2));
            C[(long)(n + 1) * M + m1] = v3 / (1.f + __expf(-v3));
        }
    }
}

// ---------------------------------------------------------------------------
// Flash attention: 64-key tiles, exp2 softmax, LDS.64 b-fragments.
// K smem [token][d] stride 72 (d pair-interleaved at producer);
// V smem [d][token] stride 72 (token pair-interleaved at producer).
// Dynamic smem: 2*(64*72) + 2*(72*72) words = 78336 B.
// Grid: (32 q-tiles of 128, 8 heads). 128 threads = 4 warps x 32 q-rows.
// ---------------------------------------------------------------------------
#define KST 72
#define VTST 72
#define KT64 64
#define FLASH_SMEM_WORDS (2 * KT64 * KST + 2 * DH * VTST)

__global__ void __launch_bounds__(128) flash_tc_kernel(
    const float* __restrict__ qkv, const float* __restrict__ vT,
    float* __restrict__ attn_out)
{
    extern __shared__ __align__(16) uint32_t smemd[];
    uint32_t* Ksm[2] = {smemd, smemd + KT64 * KST};
    uint32_t* Vsm[2] = {smemd + 2 * KT64 * KST,
                        smemd + 2 * KT64 * KST + DH * VTST};

    const int tid  = threadIdx.x;
    const int w    = tid >> 5;
    const int lane = tid & 31;
    const int g    = lane >> 2;
    const int t    = lane & 3;
    const int h    = blockIdx.y;
    const int q0   = blockIdx.x * 128;
    // fold log2(e) into the softmax scale: exp(x) = exp2(x * log2e)
    const float scale = rsqrtf((float)DH) * 1.44269504088896340736f;
    const unsigned FULL = 0xffffffffu;
    const int src1 = (lane & ~3) | (t >> 1);
    const int src2 = src1 + 2;
    const bool odd = (t & 1);

    auto stage = [&](int kt, int buf) {
        // K: 64 token-rows x 18 chunks = 1152
        const float* kb = qkv + (long)(kt * KT64) * QKVD + DIMC + h * DH;
#pragma unroll
        for (int i = 0; i < 9; i++) {
            int idx = tid + i * 128;
            {
                int row = idx / 18, c = (idx % 18) * 4;
                cp16(__cvta_generic_to_shared(&Ksm[buf][row * KST + c]),
                     kb + (long)row * QKVD + c);
            }
        }
        // V: 72 d-rows x 16 chunks = 1152 from vT[d][token]
        const float* vb = vT + (long)(h * DH) * L_TOK + (long)kt * KT64;
#pragma unroll
        for (int i = 0; i < 9; i++) {
            int idx = tid + i * 128;
            {
                int row = idx >> 4, c = (idx & 15) * 4;
                cp16(__cvta_generic_to_shared(&Vsm[buf][row * VTST + c]),
                     vb + (long)row * L_TOK + c);
            }
        }
    };

    // Q fragments (q section fp32; scale + cvt once per block)
    uint32_t qa[2][9][4];
    {
        const float* qb = qkv + (long)(q0 + w * 32) * QKVD + h * DH;
#pragma unroll
        for (int i = 0; i < 2; i++) {
            const float* qbi = qb + (long)(i * 16) * QKVD;
#pragma unroll
            for (int ks = 0; ks < 9; ks++) {
                qa[i][ks][0] = f2tf32(qbi[(long)g       * QKVD + ks * 8 + t]     * scale);
                qa[i][ks][1] = f2tf32(qbi[(long)(g + 8) * QKVD + ks * 8 + t]     * scale);
                qa[i][ks][2] = f2tf32(qbi[(long)g       * QKVD + ks * 8 + t + 4] * scale);
                qa[i][ks][3] = f2tf32(qbi[(long)(g + 8) * QKVD + ks * 8 + t + 4] * scale);
            }
        }
    }

    float o[2][9][4];
#pragma unroll
    for (int i = 0; i < 2; i++)
#pragma unroll
        for (int n = 0; n < 9; n++)
#pragma unroll
            for (int j = 0; j < 4; j++) o[i][n][j] = 0.f;
    float mx[2][2] = {{-1e30f, -1e30f}, {-1e30f, -1e30f}};
    float ls[2][2] = {{0.f, 0.f}, {0.f, 0.f}};

    stage(0, 0);
    CP_COMMIT();

    const int NT = L_TOK / KT64;  // 64
    for (int kt = 0; kt < NT; kt++) {
        CP_WAIT0();
        __syncthreads();
        if (kt + 1 < NT) {
            stage(kt + 1, (kt + 1) & 1);
            CP_COMMIT();
        }
        const uint32_t* Kb = Ksm[kt & 1];
        const uint32_t* Vb = Vsm[kt & 1];

        // --- S = Q @ K^T  (32 x 64 per warp; LDS.64 b-pairs) ---
        float s[2][8][4];
#pragma unroll
        for (int i = 0; i < 2; i++)
#pragma unroll
            for (int n = 0; n < 8; n++)
#pragma unroll
                for (int j = 0; j < 4; j++) s[i][n][j] = 0.f;

#pragma unroll
        for (int ks = 0; ks < 9; ks++) {
#pragma unroll
            for (int nn = 0; nn < 8; nn++) {
                uint2 kv = *(const uint2*)(Kb + (nn * 8 + g) * KST + ks * 8 + 2 * t);
                mma_tf32(s[0][nn], qa[0][ks], kv.x, kv.y);
                mma_tf32(s[1][nn], qa[1][ks], kv.x, kv.y);
            }
        }

        // --- online softmax (per half, exp2 domain) ---
        float corr[2][2];
#pragma unroll
        for (int i = 0; i < 2; i++) {
            float rmax0 = -1e30f, rmax1 = -1e30f;
#pragma unroll
            for (int nn = 0; nn < 8; nn++) {
                rmax0 = fmaxf(rmax0, fmaxf(s[i][nn][0], s[i][nn][1]));
                rmax1 = fmaxf(rmax1, fmaxf(s[i][nn][2], s[i][nn][3]));
            }
            rmax0 = fmaxf(rmax0, __shfl_xor_sync(FULL, rmax0, 1));
            rmax0 = fmaxf(rmax0, __shfl_xor_sync(FULL, rmax0, 2));
            rmax1 = fmaxf(rmax1, __shfl_xor_sync(FULL, rmax1, 1));
            rmax1 = fmaxf(rmax1, __shfl_xor_sync(FULL, rmax1, 2));

            float mn0 = fmaxf(mx[i][0], rmax0), mn1 = fmaxf(mx[i][1], rmax1);
            corr[i][0] = exp2f(mx[i][0] - mn0);
            corr[i][1] = exp2f(mx[i][1] - mn1);
            mx[i][0] = mn0; mx[i][1] = mn1;

            float rs0 = 0.f, rs1 = 0.f;
#pragma unroll
            for (int nn = 0; nn < 8; nn++) {
                float p0 = exp2f(s[i][nn][0] - mn0);
                float p1 = exp2f(s[i][nn][1] - mn0);
                float p2 = exp2f(s[i][nn][2] - mn1);
                float p3 = exp2f(s[i][nn][3] - mn1);
                rs0 += p0 + p1; rs1 += p2 + p3;
                s[i][nn][0] = __uint_as_float(f2tf32(p0));
                s[i][nn][1] = __uint_as_float(f2tf32(p1));
                s[i][nn][2] = __uint_as_float(f2tf32(p2));
                s[i][nn][3] = __uint_as_float(f2tf32(p3));
            }
            rs0 += __shfl_xor_sync(FULL, rs0, 1);
            rs0 += __shfl_xor_sync(FULL, rs0, 2);
            rs1 += __shfl_xor_sync(FULL, rs1, 1);
            rs1 += __shfl_xor_sync(FULL, rs1, 2);
            ls[i][0] = ls[i][0] * corr[i][0] + rs0;
            ls[i][1] = ls[i][1] * corr[i][1] + rs1;

#pragma unroll
            for (int n = 0; n < 9; n++) {
                o[i][n][0] *= corr[i][0]; o[i][n][1] *= corr[i][0];
                o[i][n][2] *= corr[i][1]; o[i][n][3] *= corr[i][1];
            }
        }

        // --- O += P @ V  (8 k-steps; LDS.64 b-pairs via token-interleave) ---
#pragma unroll
        for (int kk = 0; kk < 8; kk++) {
            uint32_t a[2][4];
#pragma unroll
            for (int i = 0; i < 2; i++) {
                float x0 = __shfl_sync(FULL, s[i][kk][0], src1);
                float x1 = __shfl_sync(FULL, s[i][kk][1], src1);
                float a0f = odd ? x1 : x0;
                float y0 = __shfl_sync(FULL, s[i][kk][0], src2);
                float y1 = __shfl_sync(FULL, s[i][kk][1], src2);
                float a2f = odd ? y1 : y0;
                float x2 = __shfl_sync(FULL, s[i][kk][2], src1);
                float x3 = __shfl_sync(FULL, s[i][kk][3], src1);
                float a1f = odd ? x3 : x2;
                float y2 = __shfl_sync(FULL, s[i][kk][2], src2);
                float y3 = __shfl_sync(FULL, s[i][kk][3], src2);
                float a3f = odd ? y3 : y2;
                a[i][0] = __float_as_uint(a0f);
                a[i][1] = __float_as_uint(a1f);
                a[i][2] = __float_as_uint(a2f);
                a[i][3] = __float_as_uint(a3f);
            }
#pragma unroll
            for (int nn = 0; nn < 9; nn++) {
                uint2 vv = *(const uint2*)(Vb + (nn * 8 + g) * VTST + kk * 8 + 2 * t);
                mma_tf32(o[0][nn], a[0], vv.x, vv.y);
                mma_tf32(o[1][nn], a[1], vv.x, vv.y);
            }
        }
    }

    // epilogue
#pragma unroll
    for (int i = 0; i < 2; i++) {
        float inv0 = 1.f / ls[i][0], inv1 = 1.f / ls[i][1];
        float* ob = attn_out + (long)(q0 + w * 32 + i * 16) * DIMC + h * DH;
#pragma unroll
        for (int nn = 0; nn < 9; nn++) {
            *(float2*)(ob + (long)g       * DIMC + nn * 8 + 2 * t) =
                make_float2(o[i][nn][0] * inv0, o[i][nn][1] * inv0);
            *(float2*)(ob + (long)(g + 8) * DIMC + nn * 8 + 2 * t) =
                make_float2(o[i][nn][2] * inv1, o[i][nn][3] * inv1);
        }
    }
}

// ---------------------------------------------------------------------------
extern "C" void kernel_launch(void* const* d_in, const int* in_sizes, int n_in,
                              void* d_out, int out_size)
{
    const float* fea    = (const float*)d_in[0];
    const float* w_qkv  = (const float*)d_in[1];
    const float* b_qkv  = (const float*)d_in[2];
    const float* w_out  = (const float*)d_in[3];
    const float* b_out  = (const float*)d_in[4];
    const float* conv_w = (const float*)d_in[5];
    float* out = (float*)d_out;

    float* x    = nullptr; cudaGetSymbolAddress((void**)&x,    g_x);
    float* qkv  = nullptr; cudaGetSymbolAddress((void**)&qkv,  g_qkv);
    float* vT   = nullptr; cudaGetSymbolAddress((void**)&vT,   g_vT);
    float* attn = nullptr; cudaGetSymbolAddress((void**)&attn, g_attn);
    float* x2   = nullptr; cudaGetSymbolAddress((void**)&x2,   g_x2);

    const int flash_smem = FLASH_SMEM_WORDS * 4;   // 78336 B
    cudaFuncSetAttribute(flash_tc_kernel,
                         cudaFuncAttributeMaxDynamicSharedMemorySize, flash_smem);

    // 1) unfold
    unfold_kernel<<<(L_TOK * DIMC + 255) / 256, 256>>>(fea, x);

    // 2) qkv = x @ w_qkv + b_qkv   (K d-interleaved tf32; V -> vT transposed)
    tf32_gemm_pipe<0, true><<<dim3(QKVD / 64, L_TOK / 128), 256>>>(
        x, w_qkv, b_qkv, nullptr, qkv, vT, L_TOK, QKVD, DIMC);

    // 3) flash attention (64-key tiles, exp2 softmax)
    flash_tc_kernel<<<dim3(L_TOK / 128, NHEADS), 128, flash_smem>>>(qkv, vT, attn);

    // 4) x2 = attn @ w_out + b_out + x
    tf32_gemm_pipe<1, false><<<dim3(DIMC / 64, L_TOK / 128), 256>>>(
        attn, w_out, b_out, x, x2, nullptr, L_TOK, DIMC, DIMC);

    // 5) out[oc,l] = silu( x2 @ conv_w^T )
    tf32_gemm_final<<<dim3(OUTC / 64, L_TOK / 128), 256>>>(
        x2, conv_w, out, L_TOK, OUTC, DIMC);
}

// round 10
// speedup vs baseline: 1.1596x; 1.1596x over previous
#include <cuda_runtime.h>
#include <cuda_bf16.h>
#include <cstdint>

#define L_TOK 4096
#define DIMC 576
#define QKVD 1728
#define NHEADS 8
#define DH 72
#define OUTC 128

// Scratch (allocation-free: __device__ globals)
__device__ float g_x[L_TOK * DIMC];       // unfold fp32 (residual)
__device__ float g_xt[L_TOK * DIMC];      // unfold tf32-bits (GEMM A)
__device__ float g_qkv[L_TOK * QKVD];     // q fp32 | k tf32-bits d-interleaved | (v unused)
__device__ float g_vT[DIMC * L_TOK];      // v tf32-bits [d][token] token-interleaved
__device__ float g_attn[L_TOK * DIMC];    // attn out, tf32-bits
__device__ float g_x2[L_TOK * DIMC];      // attn+resid, tf32-bits
__device__ float g_wqkv_t[DIMC * QKVD];   // w_qkv tf32-bits
__device__ float g_wout_t[DIMC * DIMC];   // w_out tf32-bits
__device__ float g_wconv_t[OUTC * DIMC];  // conv_w tf32-bits

// ---------------------------------------------------------------------------
// helpers
// ---------------------------------------------------------------------------
__device__ __forceinline__ uint32_t f2tf32(float x) {
    uint32_t r;
    asm("cvt.rna.tf32.f32 %0, %1;" : "=r"(r) : "f"(x));
    return r;
}

__device__ __forceinline__ void mma_tf32(float d[4],
                                         const uint32_t a[4],
                                         uint32_t b0, uint32_t b1) {
    asm volatile(
        "mma.sync.aligned.m16n8k8.row.col.f32.tf32.tf32.f32 "
        "{%0,%1,%2,%3}, {%4,%5,%6,%7}, {%8,%9}, {%0,%1,%2,%3};\n"
        : "+f"(d[0]), "+f"(d[1]), "+f"(d[2]), "+f"(d[3])
        : "r"(a[0]), "r"(a[1]), "r"(a[2]), "r"(a[3]), "r"(b0), "r"(b1));
}

__device__ __forceinline__ void cp16(uint32_t smem_addr, const void* gptr) {
    asm volatile("cp.async.cg.shared.global [%0], [%1], 16;\n"
                 :: "r"(smem_addr), "l"(gptr));
}
#define CP_COMMIT() asm volatile("cp.async.commit_group;\n" ::: "memory")
#define CP_WAIT0()  asm volatile("cp.async.wait_group 0;\n" ::: "memory")

// pair-interleave within an 8-group: positions (2i,2i+1) hold indices (i,i+4)
__device__ __forceinline__ int kvpos(int j) { return 2 * (j & 3) + (j >> 2); }

// ---------------------------------------------------------------------------
// Unfold 3x3 stride2 pad1 -> fp32 (residual) + tf32 bits (GEMM A)
// ---------------------------------------------------------------------------
__global__ void unfold_kernel(const float* __restrict__ fea,
                              float* __restrict__ x, uint32_t* __restrict__ xt) {
    int idx = blockIdx.x * blockDim.x + threadIdx.x;
    if (idx >= L_TOK * DIMC) return;
    int l = idx / DIMC, d = idx - l * DIMC;
    int c = d / 9, r = d - c * 9;
    int ki = r / 3, kj = r - ki * 3;
    int ho = l >> 6, wo = l & 63;
    int h = 2 * ho + ki - 1;
    int w = 2 * wo + kj - 1;
    float v = 0.f;
    if (h >= 0 && h < 128 && w >= 0 && w < 128)
        v = fea[c * 16384 + h * 128 + w];
    x[idx] = v;
    xt[idx] = f2tf32(v);
}

// ---------------------------------------------------------------------------
// Weight pre-conversion: out[i] = tf32_bits(in[i])
// ---------------------------------------------------------------------------
__global__ void wconv_kernel(const float* __restrict__ in,
                             uint32_t* __restrict__ out, int n) {
    int i = blockIdx.x * blockDim.x + threadIdx.x;
    if (i < n) out[i] = f2tf32(in[i]);
}

// ---------------------------------------------------------------------------
// Pipelined tf32 GEMM; A and B are PRE-CONVERTED tf32 bit patterns.
// MODE 0: +bias, CVTKV epilogue (qkv: K d-interleaved, V -> vT transposed)
// MODE 1: +bias+resid (fp32 resid/bias), output stored as tf32 BITS
// ---------------------------------------------------------------------------
#define AST 20
#define BST 72

template <int MODE, bool CVTKV>
__global__ void __launch_bounds__(256) tf32_gemm_pipe(
    const float* __restrict__ A, const float* __restrict__ B,
    const float* __restrict__ bias, const float* __restrict__ resid,
    float* __restrict__ C, float* __restrict__ vT, int M, int N, int K)
{
    __shared__ __align__(16) uint32_t As[2][128 * AST];
    __shared__ __align__(16) uint32_t Bs[2][16 * BST];

    const int tid  = threadIdx.x;
    const int lane = tid & 31;
    const int warp = tid >> 5;
    const int g = lane >> 2;
    const int t = lane & 3;
    const int wm = (warp >> 1) * 32;
    const int wn = (warp & 1) * 32;
    const int bm = blockIdx.y * 128;
    const int bn = blockIdx.x * 64;

    const int a_row0 = (tid * 2) >> 2;
    const int a_c0   = (tid * 2) & 3;
    const int a_row1 = (tid * 2 + 1) >> 2;
    const int a_c1   = (tid * 2 + 1) & 3;
    const int b_row  = tid >> 4;
    const int b_c    = tid & 15;

    auto stage = [&](int k0, int buf) {
        cp16(__cvta_generic_to_shared(&As[buf][a_row0 * AST + a_c0 * 4]),
             A + (long)(bm + a_row0) * K + k0 + a_c0 * 4);
        cp16(__cvta_generic_to_shared(&As[buf][a_row1 * AST + a_c1 * 4]),
             A + (long)(bm + a_row1) * K + k0 + a_c1 * 4);
        cp16(__cvta_generic_to_shared(&Bs[buf][b_row * BST + b_c * 4]),
             B + (long)(k0 + b_row) * N + bn + b_c * 4);
    };

    float acc[2][4][4];
#pragma unroll
    for (int i = 0; i < 2; i++)
#pragma unroll
        for (int j = 0; j < 4; j++)
#pragma unroll
            for (int f = 0; f < 4; f++) acc[i][j][f] = 0.f;

    const int ns = K / 16;
    stage(0, 0);
    CP_COMMIT();

    for (int kt = 0; kt < ns; kt++) {
        CP_WAIT0();
        __syncthreads();
        if (kt + 1 < ns) {
            stage((kt + 1) * 16, (kt + 1) & 1);
            CP_COMMIT();
        }
        const uint32_t* Ab = As[kt & 1];
        const uint32_t* Bb = Bs[kt & 1];
#pragma unroll
        for (int ks = 0; ks < 2; ks++) {
            uint32_t af[2][4];
#pragma unroll
            for (int i = 0; i < 2; i++) {
                int mb = wm + i * 16;
                af[i][0] = Ab[(mb + g)     * AST + ks * 8 + t];
                af[i][1] = Ab[(mb + g + 8) * AST + ks * 8 + t];
                af[i][2] = Ab[(mb + g)     * AST + ks * 8 + t + 4];
                af[i][3] = Ab[(mb + g + 8) * AST + ks * 8 + t + 4];
            }
#pragma unroll
            for (int j = 0; j < 4; j++) {
                uint32_t b0 = Bb[(ks * 8 + t)     * BST + wn + j * 8 + g];
                uint32_t b1 = Bb[(ks * 8 + t + 4) * BST + wn + j * 8 + g];
                mma_tf32(acc[0][j], af[0], b0, b1);
                mma_tf32(acc[1][j], af[1], b0, b1);
            }
        }
    }

    // epilogue — section is block-uniform (bn granularity 64 divides 576)
    const int sec = (!CVTKV) ? 0 : (bn >= 2 * DIMC ? 2 : (bn >= DIMC ? 1 : 0));
#pragma unroll
    for (int i = 0; i < 2; i++) {
#pragma unroll
        for (int j = 0; j < 4; j++) {
            int m0 = bm + wm + i * 16 + g;
            int m1 = m0 + 8;
            int n  = bn + wn + j * 8 + 2 * t;
            float2 bb = *(const float2*)(bias + n);
            if (MODE == 0) {
                float v00 = acc[i][j][0] + bb.x, v01 = acc[i][j][1] + bb.y;
                float v10 = acc[i][j][2] + bb.x, v11 = acc[i][j][3] + bb.y;
                if (sec == 0) {
                    // Q: fp32 (flash scales before rounding)
                    *(float2*)(C + (long)m0 * N + n) = make_float2(v00, v01);
                    *(float2*)(C + (long)m1 * N + n) = make_float2(v10, v11);
                } else if (sec == 1) {
                    // K: tf32 bits, d-interleaved within 8-group
                    uint32_t* Cu = (uint32_t*)C;
                    int base8 = bn + wn + j * 8;
                    int n0 = base8 + kvpos(2 * t);
                    int n1 = base8 + kvpos(2 * t + 1);
                    Cu[(long)m0 * N + n0] = f2tf32(v00);
                    Cu[(long)m0 * N + n1] = f2tf32(v01);
                    Cu[(long)m1 * N + n0] = f2tf32(v10);
                    Cu[(long)m1 * N + n1] = f2tf32(v11);
                } else {
                    // V: tf32 bits, transposed [d][token], token-interleaved
                    uint32_t* Vu = (uint32_t*)vT;
                    int d0 = n - 2 * DIMC;
                    int mp0 = (m0 & ~7) + kvpos(g);
                    int mp1 = mp0 + 8;
                    Vu[(long)d0 * L_TOK + mp0]       = f2tf32(v00);
                    Vu[(long)(d0 + 1) * L_TOK + mp0] = f2tf32(v01);
                    Vu[(long)d0 * L_TOK + mp1]       = f2tf32(v10);
                    Vu[(long)(d0 + 1) * L_TOK + mp1] = f2tf32(v11);
                }
            } else {
                // MODE 1: x2 = acc + bias + resid, stored as tf32 BITS
                float2 r0 = *(const float2*)(resid + (long)m0 * N + n);
                float2 r1 = *(const float2*)(resid + (long)m1 * N + n);
                uint32_t* Cu = (uint32_t*)C;
                Cu[(long)m0 * N + n]     = f2tf32(acc[i][j][0] + bb.x + r0.x);
                Cu[(long)m0 * N + n + 1] = f2tf32(acc[i][j][1] + bb.y + r0.y);
                Cu[(long)m1 * N + n]     = f2tf32(acc[i][j][2] + bb.x + r1.x);
                Cu[(long)m1 * N + n + 1] = f2tf32(acc[i][j][3] + bb.y + r1.y);
            }
        }
    }
}

// ---------------------------------------------------------------------------
// Final GEMM (TRANSB, silu, transposed store); A,B pre-converted tf32 bits
// ---------------------------------------------------------------------------
__global__ void __launch_bounds__(256) tf32_gemm_final(
    const float* __restrict__ A, const float* __restrict__ B,
    float* __restrict__ C, int M, int N, int K)
{
    __shared__ __align__(16) uint32_t As[128 * AST];
    __shared__ __align__(16) uint32_t Bs[16 * BST];

    const int tid  = threadIdx.x;
    const int lane = tid & 31;
    const int warp = tid >> 5;
    const int g = lane >> 2;
    const int t = lane & 3;
    const int wm = (warp >> 1) * 32;
    const int wn = (warp & 1) * 32;
    const int bm = blockIdx.y * 128;
    const int bn = blockIdx.x * 64;

    const int a_m = tid >> 1;
    const int a_k = (tid & 1) * 8;
    const int b_n = tid >> 2;
    const int b_k = (tid & 3) * 4;

    float acc[2][4][4];
#pragma unroll
    for (int i = 0; i < 2; i++)
#pragma unroll
        for (int j = 0; j < 4; j++)
#pragma unroll
            for (int f = 0; f < 4; f++) acc[i][j][f] = 0.f;

    for (int k0 = 0; k0 < K; k0 += 16) {
        {
            const uint32_t* Ap = (const uint32_t*)A + (long)(bm + a_m) * K + k0 + a_k;
            *(uint4*)&As[a_m * AST + a_k]     = *(const uint4*)(Ap);
            *(uint4*)&As[a_m * AST + a_k + 4] = *(const uint4*)(Ap + 4);
        }
        {
            uint4 bv = *(const uint4*)((const uint32_t*)B + (long)(bn + b_n) * K + k0 + b_k);
            Bs[(b_k + 0) * BST + b_n] = bv.x;
            Bs[(b_k + 1) * BST + b_n] = bv.y;
            Bs[(b_k + 2) * BST + b_n] = bv.z;
            Bs[(b_k + 3) * BST + b_n] = bv.w;
        }
        __syncthreads();

#pragma unroll
        for (int ks = 0; ks < 2; ks++) {
            uint32_t af[2][4];
#pragma unroll
            for (int i = 0; i < 2; i++) {
                int mb = wm + i * 16;
                af[i][0] = As[(mb + g)     * AST + ks * 8 + t];
                af[i][1] = As[(mb + g + 8) * AST + ks * 8 + t];
                af[i][2] = As[(mb + g)     * AST + ks * 8 + t + 4];
                af[i][3] = As[(mb + g + 8) * AST + ks * 8 + t + 4];
            }
#pragma unroll
            for (int j = 0; j < 4; j++) {
                uint32_t b0 = Bs[(ks * 8 + t)     * BST + wn + j * 8 + g];
                uint32_t b1 = Bs[(ks * 8 + t + 4) * BST + wn + j * 8 + g];
                mma_tf32(acc[0][j], af[0], b0, b1);
                mma_tf32(acc[1][j], af[1], b0, b1);
            }
        }
        __syncthreads();
    }

#pragma unroll
    for (int i = 0; i < 2; i++) {
#pragma unroll
        for (int j = 0; j < 4; j++) {
            int m0 = bm + wm + i * 16 + g;
            int m1 = m0 + 8;
            int n  = bn + wn + j * 8 + 2 * t;
            float v0 = acc[i][j][0], v1 = acc[i][j][1];
            float v2 = acc[i][j][2], v3 = acc[i][j][3];
            C[(long)n * M + m0]       = v0 / (1.f + __expf(-v0));
            C[(long)(n + 1) * M + m0] = v1 / (1.f + __expf(-v1));
            C[(long)n * M + m1]       = v2 / (1.f + __expf(-v2));
            C[(long)(n + 1) * M + m1] = v3 / (1.f + __expf(-v3));
        }
    }
}

// ---------------------------------------------------------------------------
// Flash attention (R8 structure): 32-key tiles, exp2 softmax, LDS.64 b-frags.
// K smem [token][d] stride 72 (d pair-interleaved at producer);
// V smem [d][token] stride 40 (token pair-interleaved at producer).
// Output attn stored as tf32 BITS (consumed only by out-proj GEMM).
// ---------------------------------------------------------------------------
#define KST 72
#define VTST 40
#define KT32 32

__global__ void __launch_bounds__(128) flash_tc_kernel(
    const float* __restrict__ qkv, const float* __restrict__ vT,
    float* __restrict__ attn_out)
{
    __shared__ __align__(16) uint32_t Ksm[2][KT32 * KST];
    __shared__ __align__(16) uint32_t Vsm[2][DH * VTST];

    const int tid  = threadIdx.x;
    const int w    = tid >> 5;
    const int lane = tid & 31;
    const int g    = lane >> 2;
    const int t    = lane & 3;
    const int h    = blockIdx.y;
    const int q0   = blockIdx.x * 128;
    const float scale = rsqrtf((float)DH) * 1.44269504088896340736f;  // log2e folded
    const unsigned FULL = 0xffffffffu;
    const int src1 = (lane & ~3) | (t >> 1);
    const int src2 = src1 + 2;
    const bool odd = (t & 1);

    auto stage = [&](int kt, int buf) {
        const float* kb = qkv + (long)(kt * KT32) * QKVD + DIMC + h * DH;
#pragma unroll
        for (int i = 0; i < 5; i++) {
            int idx = tid + i * 128;
            if (idx < 576) {
                int row = idx / 18, c = (idx % 18) * 4;
                cp16(__cvta_generic_to_shared(&Ksm[buf][row * KST + c]),
                     kb + (long)row * QKVD + c);
            }
        }
        const float* vb = vT + (long)(h * DH) * L_TOK + (long)kt * KT32;
#pragma unroll
        for (int i = 0; i < 5; i++) {
            int idx = tid + i * 128;
            if (idx < 576) {
                int row = idx >> 3, c = (idx & 7) * 4;
                cp16(__cvta_generic_to_shared(&Vsm[buf][row * VTST + c]),
                     vb + (long)row * L_TOK + c);
            }
        }
    };

    // Q fragments (fp32 section; scale+cvt once per block)
    uint32_t qa[2][9][4];
    {
        const float* qb = qkv + (long)(q0 + w * 32) * QKVD + h * DH;
#pragma unroll
        for (int i = 0; i < 2; i++) {
            const float* qbi = qb + (long)(i * 16) * QKVD;
#pragma unroll
            for (int ks = 0; ks < 9; ks++) {
                qa[i][ks][0] = f2tf32(qbi[(long)g       * QKVD + ks * 8 + t]     * scale);
                qa[i][ks][1] = f2tf32(qbi[(long)(g + 8) * QKVD + ks * 8 + t]     * scale);
                qa[i][ks][2] = f2tf32(qbi[(long)g       * QKVD + ks * 8 + t + 4] * scale);
                qa[i][ks][3] = f2tf32(qbi[(long)(g + 8) * QKVD + ks * 8 + t + 4] * scale);
            }
        }
    }

    float o[2][9][4];
#pragma unroll
    for (int i = 0; i < 2; i++)
#pragma unroll
        for (int n = 0; n < 9; n++)
#pragma unroll
            for (int j = 0; j < 4; j++) o[i][n][j] = 0.f;
    float mx[2][2] = {{-1e30f, -1e30f}, {-1e30f, -1e30f}};
    float ls[2][2] = {{0.f, 0.f}, {0.f, 0.f}};

    stage(0, 0);
    CP_COMMIT();

    const int NT = L_TOK / KT32;  // 128
    for (int kt = 0; kt < NT; kt++) {
        CP_WAIT0();
        __syncthreads();
        if (kt + 1 < NT) {
            stage(kt + 1, (kt + 1) & 1);
            CP_COMMIT();
        }
        const uint32_t* Kb = Ksm[kt & 1];
        const uint32_t* Vb = Vsm[kt & 1];

        // --- S = Q @ K^T ---
        float s[2][4][4];
#pragma unroll
        for (int i = 0; i < 2; i++)
#pragma unroll
            for (int n = 0; n < 4; n++)
#pragma unroll
                for (int j = 0; j < 4; j++) s[i][n][j] = 0.f;

#pragma unroll
        for (int ks = 0; ks < 9; ks++) {
#pragma unroll
            for (int nn = 0; nn < 4; nn++) {
                uint2 kv = *(const uint2*)(Kb + (nn * 8 + g) * KST + ks * 8 + 2 * t);
                mma_tf32(s[0][nn], qa[0][ks], kv.x, kv.y);
                mma_tf32(s[1][nn], qa[1][ks], kv.x, kv.y);
            }
        }

        // --- online softmax (exp2 domain) ---
        float corr[2][2];
#pragma unroll
        for (int i = 0; i < 2; i++) {
            float rmax0 = -1e30f, rmax1 = -1e30f;
#pragma unroll
            for (int nn = 0; nn < 4; nn++) {
                rmax0 = fmaxf(rmax0, fmaxf(s[i][nn][0], s[i][nn][1]));
                rmax1 = fmaxf(rmax1, fmaxf(s[i][nn][2], s[i][nn][3]));
            }
            rmax0 = fmaxf(rmax0, __shfl_xor_sync(FULL, rmax0, 1));
            rmax0 = fmaxf(rmax0, __shfl_xor_sync(FULL, rmax0, 2));
            rmax1 = fmaxf(rmax1, __shfl_xor_sync(FULL, rmax1, 1));
            rmax1 = fmaxf(rmax1, __shfl_xor_sync(FULL, rmax1, 2));

            float mn0 = fmaxf(mx[i][0], rmax0), mn1 = fmaxf(mx[i][1], rmax1);
            corr[i][0] = exp2f(mx[i][0] - mn0);
            corr[i][1] = exp2f(mx[i][1] - mn1);
            mx[i][0] = mn0; mx[i][1] = mn1;

            float rs0 = 0.f, rs1 = 0.f;
#pragma unroll
            for (int nn = 0; nn < 4; nn++) {
                float p0 = exp2f(s[i][nn][0] - mn0);
                float p1 = exp2f(s[i][nn][1] - mn0);
                float p2 = exp2f(s[i][nn][2] - mn1);
                float p3 = exp2f(s[i][nn][3] - mn1);
                rs0 += p0 + p1; rs1 += p2 + p3;
                s[i][nn][0] = __uint_as_float(f2tf32(p0));
                s[i][nn][1] = __uint_as_float(f2tf32(p1));
                s[i][nn][2] = __uint_as_float(f2tf32(p2));
                s[i][nn][3] = __uint_as_float(f2tf32(p3));
            }
            rs0 += __shfl_xor_sync(FULL, rs0, 1);
            rs0 += __shfl_xor_sync(FULL, rs0, 2);
            rs1 += __shfl_xor_sync(FULL, rs1, 1);
            rs1 += __shfl_xor_sync(FULL, rs1, 2);
            ls[i][0] = ls[i][0] * corr[i][0] + rs0;
            ls[i][1] = ls[i][1] * corr[i][1] + rs1;

#pragma unroll
            for (int n = 0; n < 9; n++) {
                o[i][n][0] *= corr[i][0]; o[i][n][1] *= corr[i][0];
                o[i][n][2] *= corr[i][1]; o[i][n][3] *= corr[i][1];
            }
        }

        // --- O += P @ V ---
#pragma unroll
        for (int kk = 0; kk < 4; kk++) {
            uint32_t a[2][4];
#pragma unroll
            for (int i = 0; i < 2; i++) {
                float x0 = __shfl_sync(FULL, s[i][kk][0], src1);
                float x1 = __shfl_sync(FULL, s[i][kk][1], src1);
                float a0f = odd ? x1 : x0;
                float y0 = __shfl_sync(FULL, s[i][kk][0], src2);
                float y1 = __shfl_sync(FULL, s[i][kk][1], src2);
                float a2f = odd ? y1 : y0;
                float x2 = __shfl_sync(FULL, s[i][kk][2], src1);
                float x3 = __shfl_sync(FULL, s[i][kk][3], src1);
                float a1f = odd ? x3 : x2;
                float y2 = __shfl_sync(FULL, s[i][kk][2], src2);
                float y3 = __shfl_sync(FULL, s[i][kk][3], src2);
                float a3f = odd ? y3 : y2;
                a[i][0] = __float_as_uint(a0f);
                a[i][1] = __float_as_uint(a1f);
                a[i][2] = __float_as_uint(a2f);
                a[i][3] = __float_as_uint(a3f);
            }
#pragma unroll
            for (int nn = 0; nn < 9; nn++) {
                uint2 vv = *(const uint2*)(Vb + (nn * 8 + g) * VTST + kk * 8 + 2 * t);
                mma_tf32(o[0][nn], a[0], vv.x, vv.y);
                mma_tf32(o[1][nn], a[1], vv.x, vv.y);
            }
        }
    }

    // epilogue: store attn as tf32 BITS (consumed by out-proj GEMM A)
#pragma unroll
    for (int i = 0; i < 2; i++) {
        float inv0 = 1.f / ls[i][0], inv1 = 1.f / ls[i][1];
        uint32_t* ob = (uint32_t*)attn_out + (long)(q0 + w * 32 + i * 16) * DIMC + h * DH;
#pragma unroll
        for (int nn = 0; nn < 9; nn++) {
            *(uint2*)(ob + (long)g * DIMC + nn * 8 + 2 * t) =
                make_uint2(f2tf32(o[i][nn][0] * inv0), f2tf32(o[i][nn][1] * inv0));
            *(uint2*)(ob + (long)(g + 8) * DIMC + nn * 8 + 2 * t) =
                make_uint2(f2tf32(o[i][nn][2] * inv1), f2tf32(o[i][nn][3] * inv1));
        }
    }
}

// ---------------------------------------------------------------------------
extern "C" void kernel_launch(void* const* d_in, const int* in_sizes, int n_in,
                              void* d_out, int out_size)
{
    const float* fea    = (const float*)d_in[0];
    const float* w_qkv  = (const float*)d_in[1];
    const float* b_qkv  = (const float*)d_in[2];
    const float* w_out  = (const float*)d_in[3];
    const float* b_out  = (const float*)d_in[4];
    const float* conv_w = (const float*)d_in[5];
    float* out = (float*)d_out;

    float* x     = nullptr; cudaGetSymbolAddress((void**)&x,     g_x);
    float* xt    = nullptr; cudaGetSymbolAddress((void**)&xt,    g_xt);
    float* qkv   = nullptr; cudaGetSymbolAddress((void**)&qkv,   g_qkv);
    float* vT    = nullptr; cudaGetSymbolAddress((void**)&vT,    g_vT);
    float* attn  = nullptr; cudaGetSymbolAddress((void**)&attn,  g_attn);
    float* x2    = nullptr; cudaGetSymbolAddress((void**)&x2,    g_x2);
    float* wqkvt = nullptr; cudaGetSymbolAddress((void**)&wqkvt, g_wqkv_t);
    float* woutt = nullptr; cudaGetSymbolAddress((void**)&woutt, g_wout_t);
    float* wcnvt = nullptr; cudaGetSymbolAddress((void**)&wcnvt, g_wconv_t);

    // 0) pre-convert weights to tf32 bits
    wconv_kernel<<<(DIMC * QKVD + 255) / 256, 256>>>(w_qkv, (uint32_t*)wqkvt, DIMC * QKVD);
    wconv_kernel<<<(DIMC * DIMC + 255) / 256, 256>>>(w_out, (uint32_t*)woutt, DIMC * DIMC);
    wconv_kernel<<<(OUTC * DIMC + 255) / 256, 256>>>(conv_w, (uint32_t*)wcnvt, OUTC * DIMC);

    // 1) unfold -> fp32 + tf32 bits
    unfold_kernel<<<(L_TOK * DIMC + 255) / 256, 256>>>(fea, x, (uint32_t*)xt);

    // 2) qkv = xt @ wqkv_t + b_qkv  (Q fp32; K d-interleaved bits; V -> vT)
    tf32_gemm_pipe<0, true><<<dim3(QKVD / 64, L_TOK / 128), 256>>>(
        xt, wqkvt, b_qkv, nullptr, qkv, vT, L_TOK, QKVD, DIMC);

    // 3) flash attention -> attn (tf32 bits)
    flash_tc_kernel<<<dim3(L_TOK / 128, NHEADS), 128>>>(qkv, vT, attn);

    // 4) x2 = attn @ wout_t + b_out + x  (stored as tf32 bits)
    tf32_gemm_pipe<1, false><<<dim3(DIMC / 64, L_TOK / 128), 256>>>(
        attn, woutt, b_out, x, x2, nullptr, L_TOK, DIMC, DIMC);

    // 5) out[oc,l] = silu( x2 @ wconv_t^T )
    tf32_gemm_final<<<dim3(OUTC / 64, L_TOK / 128), 256>>>(
        x2, wcnvt, out, L_TOK, OUTC, DIMC);
}

// round 11
// speedup vs baseline: 1.2380x; 1.0676x over previous
#include <cuda_runtime.h>
#include <cuda_bf16.h>
#include <cstdint>

#define L_TOK 4096
#define DIMC 576
#define QKVD 1728
#define NHEADS 8
#define DH 72
#define OUTC 128

// Scratch (allocation-free: __device__ globals)
__device__ float g_x[L_TOK * DIMC];       // unfold fp32 (residual)
__device__ float g_xt[L_TOK * DIMC];      // unfold tf32-bits (GEMM A)
__device__ float g_qkv[L_TOK * QKVD];     // q fp32 | k tf32-bits d-interleaved | (v unused)
__device__ float g_vT[DIMC * L_TOK];      // v tf32-bits [d][token] NATURAL token order
__device__ float g_attn[L_TOK * DIMC];    // attn out, tf32-bits
__device__ float g_x2[L_TOK * DIMC];      // attn+resid, tf32-bits
__device__ float g_wqkv_t[DIMC * QKVD];   // w_qkv tf32-bits
__device__ float g_wout_t[DIMC * DIMC];   // w_out tf32-bits
__device__ float g_wconv_t[OUTC * DIMC];  // conv_w tf32-bits

// ---------------------------------------------------------------------------
// helpers
// ---------------------------------------------------------------------------
__device__ __forceinline__ uint32_t f2tf32(float x) {
    uint32_t r;
    asm("cvt.rna.tf32.f32 %0, %1;" : "=r"(r) : "f"(x));
    return r;
}

__device__ __forceinline__ void mma_tf32(float d[4],
                                         const uint32_t a[4],
                                         uint32_t b0, uint32_t b1) {
    asm volatile(
        "mma.sync.aligned.m16n8k8.row.col.f32.tf32.tf32.f32 "
        "{%0,%1,%2,%3}, {%4,%5,%6,%7}, {%8,%9}, {%0,%1,%2,%3};\n"
        : "+f"(d[0]), "+f"(d[1]), "+f"(d[2]), "+f"(d[3])
        : "r"(a[0]), "r"(a[1]), "r"(a[2]), "r"(a[3]), "r"(b0), "r"(b1));
}

// PV variant: a-operand given as the S c-fragment registers directly.
// k-slot permutation sigma = [0,2,4,6,1,3,5,7]: a = {s0, s2, s1, s3}.
__device__ __forceinline__ void mma_tf32_pv(float d[4], const float s[4],
                                            uint32_t b0, uint32_t b1) {
    asm volatile(
        "mma.sync.aligned.m16n8k8.row.col.f32.tf32.tf32.f32 "
        "{%0,%1,%2,%3}, {%4,%5,%6,%7}, {%8,%9}, {%0,%1,%2,%3};\n"
        : "+f"(d[0]), "+f"(d[1]), "+f"(d[2]), "+f"(d[3])
        : "r"(__float_as_uint(s[0])), "r"(__float_as_uint(s[2])),
          "r"(__float_as_uint(s[1])), "r"(__float_as_uint(s[3])),
          "r"(b0), "r"(b1));
}

__device__ __forceinline__ void cp16(uint32_t smem_addr, const void* gptr) {
    asm volatile("cp.async.cg.shared.global [%0], [%1], 16;\n"
                 :: "r"(smem_addr), "l"(gptr));
}
#define CP_COMMIT() asm volatile("cp.async.commit_group;\n" ::: "memory")
#define CP_WAIT0()  asm volatile("cp.async.wait_group 0;\n" ::: "memory")

// pair-interleave within an 8-group: positions (2i,2i+1) hold indices (i,i+4)
__device__ __forceinline__ int kvpos(int j) { return 2 * (j & 3) + (j >> 2); }

// ---------------------------------------------------------------------------
// Unfold 3x3 stride2 pad1 -> fp32 (residual) + tf32 bits (GEMM A)
// ---------------------------------------------------------------------------
__global__ void unfold_kernel(const float* __restrict__ fea,
                              float* __restrict__ x, uint32_t* __restrict__ xt) {
    int idx = blockIdx.x * blockDim.x + threadIdx.x;
    if (idx >= L_TOK * DIMC) return;
    int l = idx / DIMC, d = idx - l * DIMC;
    int c = d / 9, r = d - c * 9;
    int ki = r / 3, kj = r - ki * 3;
    int ho = l >> 6, wo = l & 63;
    int h = 2 * ho + ki - 1;
    int w = 2 * wo + kj - 1;
    float v = 0.f;
    if (h >= 0 && h < 128 && w >= 0 && w < 128)
        v = fea[c * 16384 + h * 128 + w];
    x[idx] = v;
    xt[idx] = f2tf32(v);
}

// ---------------------------------------------------------------------------
// Weight pre-conversion
// ---------------------------------------------------------------------------
__global__ void wconv_kernel(const float* __restrict__ in,
                             uint32_t* __restrict__ out, int n) {
    int i = blockIdx.x * blockDim.x + threadIdx.x;
    if (i < n) out[i] = f2tf32(in[i]);
}

// ---------------------------------------------------------------------------
// Pipelined tf32 GEMM; A and B are PRE-CONVERTED tf32 bit patterns.
// MODE 0: +bias, CVTKV epilogue (qkv: K d-interleaved, V -> vT natural order)
// MODE 1: +bias+resid (fp32), output stored as tf32 BITS
// ---------------------------------------------------------------------------
#define AST 20
#define BST 72

template <int MODE, bool CVTKV>
__global__ void __launch_bounds__(256) tf32_gemm_pipe(
    const float* __restrict__ A, const float* __restrict__ B,
    const float* __restrict__ bias, const float* __restrict__ resid,
    float* __restrict__ C, float* __restrict__ vT, int M, int N, int K)
{
    __shared__ __align__(16) uint32_t As[2][128 * AST];
    __shared__ __align__(16) uint32_t Bs[2][16 * BST];

    const int tid  = threadIdx.x;
    const int lane = tid & 31;
    const int warp = tid >> 5;
    const int g = lane >> 2;
    const int t = lane & 3;
    const int wm = (warp >> 1) * 32;
    const int wn = (warp & 1) * 32;
    const int bm = blockIdx.y * 128;
    const int bn = blockIdx.x * 64;

    const int a_row0 = (tid * 2) >> 2;
    const int a_c0   = (tid * 2) & 3;
    const int a_row1 = (tid * 2 + 1) >> 2;
    const int a_c1   = (tid * 2 + 1) & 3;
    const int b_row  = tid >> 4;
    const int b_c    = tid & 15;

    auto stage = [&](int k0, int buf) {
        cp16(__cvta_generic_to_shared(&As[buf][a_row0 * AST + a_c0 * 4]),
             A + (long)(bm + a_row0) * K + k0 + a_c0 * 4);
        cp16(__cvta_generic_to_shared(&As[buf][a_row1 * AST + a_c1 * 4]),
             A + (long)(bm + a_row1) * K + k0 + a_c1 * 4);
        cp16(__cvta_generic_to_shared(&Bs[buf][b_row * BST + b_c * 4]),
             B + (long)(k0 + b_row) * N + bn + b_c * 4);
    };

    float acc[2][4][4];
#pragma unroll
    for (int i = 0; i < 2; i++)
#pragma unroll
        for (int j = 0; j < 4; j++)
#pragma unroll
            for (int f = 0; f < 4; f++) acc[i][j][f] = 0.f;

    const int ns = K / 16;
    stage(0, 0);
    CP_COMMIT();

    for (int kt = 0; kt < ns; kt++) {
        CP_WAIT0();
        __syncthreads();
        if (kt + 1 < ns) {
            stage((kt + 1) * 16, (kt + 1) & 1);
            CP_COMMIT();
        }
        const uint32_t* Ab = As[kt & 1];
        const uint32_t* Bb = Bs[kt & 1];
#pragma unroll
        for (int ks = 0; ks < 2; ks++) {
            uint32_t af[2][4];
#pragma unroll
            for (int i = 0; i < 2; i++) {
                int mb = wm + i * 16;
                af[i][0] = Ab[(mb + g)     * AST + ks * 8 + t];
                af[i][1] = Ab[(mb + g + 8) * AST + ks * 8 + t];
                af[i][2] = Ab[(mb + g)     * AST + ks * 8 + t + 4];
                af[i][3] = Ab[(mb + g + 8) * AST + ks * 8 + t + 4];
            }
#pragma unroll
            for (int j = 0; j < 4; j++) {
                uint32_t b0 = Bb[(ks * 8 + t)     * BST + wn + j * 8 + g];
                uint32_t b1 = Bb[(ks * 8 + t + 4) * BST + wn + j * 8 + g];
                mma_tf32(acc[0][j], af[0], b0, b1);
                mma_tf32(acc[1][j], af[1], b0, b1);
            }
        }
    }

    // epilogue — section is block-uniform (bn granularity 64 divides 576)
    const int sec = (!CVTKV) ? 0 : (bn >= 2 * DIMC ? 2 : (bn >= DIMC ? 1 : 0));
#pragma unroll
    for (int i = 0; i < 2; i++) {
#pragma unroll
        for (int j = 0; j < 4; j++) {
            int m0 = bm + wm + i * 16 + g;
            int m1 = m0 + 8;
            int n  = bn + wn + j * 8 + 2 * t;
            float2 bb = *(const float2*)(bias + n);
            if (MODE == 0) {
                float v00 = acc[i][j][0] + bb.x, v01 = acc[i][j][1] + bb.y;
                float v10 = acc[i][j][2] + bb.x, v11 = acc[i][j][3] + bb.y;
                if (sec == 0) {
                    // Q: fp32 (flash scales before rounding)
                    *(float2*)(C + (long)m0 * N + n) = make_float2(v00, v01);
                    *(float2*)(C + (long)m1 * N + n) = make_float2(v10, v11);
                } else if (sec == 1) {
                    // K: tf32 bits, d-interleaved within 8-group
                    uint32_t* Cu = (uint32_t*)C;
                    int base8 = bn + wn + j * 8;
                    int n0 = base8 + kvpos(2 * t);
                    int n1 = base8 + kvpos(2 * t + 1);
                    Cu[(long)m0 * N + n0] = f2tf32(v00);
                    Cu[(long)m0 * N + n1] = f2tf32(v01);
                    Cu[(long)m1 * N + n0] = f2tf32(v10);
                    Cu[(long)m1 * N + n1] = f2tf32(v11);
                } else {
                    // V: tf32 bits, transposed [d][token], NATURAL token order
                    uint32_t* Vu = (uint32_t*)vT;
                    int d0 = n - 2 * DIMC;
                    Vu[(long)d0 * L_TOK + m0]       = f2tf32(v00);
                    Vu[(long)(d0 + 1) * L_TOK + m0] = f2tf32(v01);
                    Vu[(long)d0 * L_TOK + m1]       = f2tf32(v10);
                    Vu[(long)(d0 + 1) * L_TOK + m1] = f2tf32(v11);
                }
            } else {
                // MODE 1: x2 = acc + bias + resid, stored as tf32 BITS
                float2 r0 = *(const float2*)(resid + (long)m0 * N + n);
                float2 r1 = *(const float2*)(resid + (long)m1 * N + n);
                uint32_t* Cu = (uint32_t*)C;
                Cu[(long)m0 * N + n]     = f2tf32(acc[i][j][0] + bb.x + r0.x);
                Cu[(long)m0 * N + n + 1] = f2tf32(acc[i][j][1] + bb.y + r0.y);
                Cu[(long)m1 * N + n]     = f2tf32(acc[i][j][2] + bb.x + r1.x);
                Cu[(long)m1 * N + n + 1] = f2tf32(acc[i][j][3] + bb.y + r1.y);
            }
        }
    }
}

// ---------------------------------------------------------------------------
// Final GEMM (TRANSB, silu, transposed store); A,B pre-converted tf32 bits
// ---------------------------------------------------------------------------
__global__ void __launch_bounds__(256) tf32_gemm_final(
    const float* __restrict__ A, const float* __restrict__ B,
    float* __restrict__ C, int M, int N, int K)
{
    __shared__ __align__(16) uint32_t As[128 * AST];
    __shared__ __align__(16) uint32_t Bs[16 * BST];

    const int tid  = threadIdx.x;
    const int lane = tid & 31;
    const int warp = tid >> 5;
    const int g = lane >> 2;
    const int t = lane & 3;
    const int wm = (warp >> 1) * 32;
    const int wn = (warp & 1) * 32;
    const int bm = blockIdx.y * 128;
    const int bn = blockIdx.x * 64;

    const int a_m = tid >> 1;
    const int a_k = (tid & 1) * 8;
    const int b_n = tid >> 2;
    const int b_k = (tid & 3) * 4;

    float acc[2][4][4];
#pragma unroll
    for (int i = 0; i < 2; i++)
#pragma unroll
        for (int j = 0; j < 4; j++)
#pragma unroll
            for (int f = 0; f < 4; f++) acc[i][j][f] = 0.f;

    for (int k0 = 0; k0 < K; k0 += 16) {
        {
            const uint32_t* Ap = (const uint32_t*)A + (long)(bm + a_m) * K + k0 + a_k;
            *(uint4*)&As[a_m * AST + a_k]     = *(const uint4*)(Ap);
            *(uint4*)&As[a_m * AST + a_k + 4] = *(const uint4*)(Ap + 4);
        }
        {
            uint4 bv = *(const uint4*)((const uint32_t*)B + (long)(bn + b_n) * K + k0 + b_k);
            Bs[(b_k + 0) * BST + b_n] = bv.x;
            Bs[(b_k + 1) * BST + b_n] = bv.y;
            Bs[(b_k + 2) * BST + b_n] = bv.z;
            Bs[(b_k + 3) * BST + b_n] = bv.w;
        }
        __syncthreads();

#pragma unroll
        for (int ks = 0; ks < 2; ks++) {
            uint32_t af[2][4];
#pragma unroll
            for (int i = 0; i < 2; i++) {
                int mb = wm + i * 16;
                af[i][0] = As[(mb + g)     * AST + ks * 8 + t];
                af[i][1] = As[(mb + g + 8) * AST + ks * 8 + t];
                af[i][2] = As[(mb + g)     * AST + ks * 8 + t + 4];
                af[i][3] = As[(mb + g + 8) * AST + ks * 8 + t + 4];
            }
#pragma unroll
            for (int j = 0; j < 4; j++) {
                uint32_t b0 = Bs[(ks * 8 + t)     * BST + wn + j * 8 + g];
                uint32_t b1 = Bs[(ks * 8 + t + 4) * BST + wn + j * 8 + g];
                mma_tf32(acc[0][j], af[0], b0, b1);
                mma_tf32(acc[1][j], af[1], b0, b1);
            }
        }
        __syncthreads();
    }

#pragma unroll
    for (int i = 0; i < 2; i++) {
#pragma unroll
        for (int j = 0; j < 4; j++) {
            int m0 = bm + wm + i * 16 + g;
            int m1 = m0 + 8;
            int n  = bn + wn + j * 8 + 2 * t;
            float v0 = acc[i][j][0], v1 = acc[i][j][1];
            float v2 = acc[i][j][2], v3 = acc[i][j][3];
            C[(long)n * M + m0]       = v0 / (1.f + __expf(-v0));
            C[(long)(n + 1) * M + m0] = v1 / (1.f + __expf(-v1));
            C[(long)n * M + m1]       = v2 / (1.f + __expf(-v2));
            C[(long)(n + 1) * M + m1] = v3 / (1.f + __expf(-v3));
        }
    }
}

// ---------------------------------------------------------------------------
// Flash attention: 32-key tiles, exp2 softmax, LDS.64 b-frags,
// SHUFFLE-FREE PV via k-slot permutation (P c-frag fed directly as a-frag;
// V in natural token order).
// ---------------------------------------------------------------------------
#define KST 72
#define VTST 40
#define KT32 32

__global__ void __launch_bounds__(128) flash_tc_kernel(
    const float* __restrict__ qkv, const float* __restrict__ vT,
    float* __restrict__ attn_out)
{
    __shared__ __align__(16) uint32_t Ksm[2][KT32 * KST];
    __shared__ __align__(16) uint32_t Vsm[2][DH * VTST];

    const int tid  = threadIdx.x;
    const int w    = tid >> 5;
    const int lane = tid & 31;
    const int g    = lane >> 2;
    const int t    = lane & 3;
    const int h    = blockIdx.y;
    const int q0   = blockIdx.x * 128;
    const float scale = rsqrtf((float)DH) * 1.44269504088896340736f;  // log2e folded
    const unsigned FULL = 0xffffffffu;

    auto stage = [&](int kt, int buf) {
        const float* kb = qkv + (long)(kt * KT32) * QKVD + DIMC + h * DH;
#pragma unroll
        for (int i = 0; i < 5; i++) {
            int idx = tid + i * 128;
            if (idx < 576) {
                int row = idx / 18, c = (idx % 18) * 4;
                cp16(__cvta_generic_to_shared(&Ksm[buf][row * KST + c]),
                     kb + (long)row * QKVD + c);
            }
        }
        const float* vb = vT + (long)(h * DH) * L_TOK + (long)kt * KT32;
#pragma unroll
        for (int i = 0; i < 5; i++) {
            int idx = tid + i * 128;
            if (idx < 576) {
                int row = idx >> 3, c = (idx & 7) * 4;
                cp16(__cvta_generic_to_shared(&Vsm[buf][row * VTST + c]),
                     vb + (long)row * L_TOK + c);
            }
        }
    };

    // Q fragments (fp32 section; scale+cvt once per block)
    uint32_t qa[2][9][4];
    {
        const float* qb = qkv + (long)(q0 + w * 32) * QKVD + h * DH;
#pragma unroll
        for (int i = 0; i < 2; i++) {
            const float* qbi = qb + (long)(i * 16) * QKVD;
#pragma unroll
            for (int ks = 0; ks < 9; ks++) {
                qa[i][ks][0] = f2tf32(qbi[(long)g       * QKVD + ks * 8 + t]     * scale);
                qa[i][ks][1] = f2tf32(qbi[(long)(g + 8) * QKVD + ks * 8 + t]     * scale);
                qa[i][ks][2] = f2tf32(qbi[(long)g       * QKVD + ks * 8 + t + 4] * scale);
                qa[i][ks][3] = f2tf32(qbi[(long)(g + 8) * QKVD + ks * 8 + t + 4] * scale);
            }
        }
    }

    float o[2][9][4];
#pragma unroll
    for (int i = 0; i < 2; i++)
#pragma unroll
        for (int n = 0; n < 9; n++)
#pragma unroll
            for (int j = 0; j < 4; j++) o[i][n][j] = 0.f;
    float mx[2][2] = {{-1e30f, -1e30f}, {-1e30f, -1e30f}};
    float ls[2][2] = {{0.f, 0.f}, {0.f, 0.f}};

    stage(0, 0);
    CP_COMMIT();

    const int NT = L_TOK / KT32;  // 128
    for (int kt = 0; kt < NT; kt++) {
        CP_WAIT0();
        __syncthreads();
        if (kt + 1 < NT) {
            stage(kt + 1, (kt + 1) & 1);
            CP_COMMIT();
        }
        const uint32_t* Kb = Ksm[kt & 1];
        const uint32_t* Vb = Vsm[kt & 1];

        // --- S = Q @ K^T ---
        float s[2][4][4];
#pragma unroll
        for (int i = 0; i < 2; i++)
#pragma unroll
            for (int n = 0; n < 4; n++)
#pragma unroll
                for (int j = 0; j < 4; j++) s[i][n][j] = 0.f;

#pragma unroll
        for (int ks = 0; ks < 9; ks++) {
#pragma unroll
            for (int nn = 0; nn < 4; nn++) {
                uint2 kv = *(const uint2*)(Kb + (nn * 8 + g) * KST + ks * 8 + 2 * t);
                mma_tf32(s[0][nn], qa[0][ks], kv.x, kv.y);
                mma_tf32(s[1][nn], qa[1][ks], kv.x, kv.y);
            }
        }

        // --- online softmax (exp2 domain) ---
        float corr[2][2];
#pragma unroll
        for (int i = 0; i < 2; i++) {
            float rmax0 = -1e30f, rmax1 = -1e30f;
#pragma unroll
            for (int nn = 0; nn < 4; nn++) {
                rmax0 = fmaxf(rmax0, fmaxf(s[i][nn][0], s[i][nn][1]));
                rmax1 = fmaxf(rmax1, fmaxf(s[i][nn][2], s[i][nn][3]));
            }
            rmax0 = fmaxf(rmax0, __shfl_xor_sync(FULL, rmax0, 1));
            rmax0 = fmaxf(rmax0, __shfl_xor_sync(FULL, rmax0, 2));
            rmax1 = fmaxf(rmax1, __shfl_xor_sync(FULL, rmax1, 1));
            rmax1 = fmaxf(rmax1, __shfl_xor_sync(FULL, rmax1, 2));

            float mn0 = fmaxf(mx[i][0], rmax0), mn1 = fmaxf(mx[i][1], rmax1);
            corr[i][0] = exp2f(mx[i][0] - mn0);
            corr[i][1] = exp2f(mx[i][1] - mn1);
            mx[i][0] = mn0; mx[i][1] = mn1;

            float rs0 = 0.f, rs1 = 0.f;
#pragma unroll
            for (int nn = 0; nn < 4; nn++) {
                float p0 = exp2f(s[i][nn][0] - mn0);
                float p1 = exp2f(s[i][nn][1] - mn0);
                float p2 = exp2f(s[i][nn][2] - mn1);
                float p3 = exp2f(s[i][nn][3] - mn1);
                rs0 += p0 + p1; rs1 += p2 + p3;
                s[i][nn][0] = __uint_as_float(f2tf32(p0));
                s[i][nn][1] = __uint_as_float(f2tf32(p1));
                s[i][nn][2] = __uint_as_float(f2tf32(p2));
                s[i][nn][3] = __uint_as_float(f2tf32(p3));
            }
            rs0 += __shfl_xor_sync(FULL, rs0, 1);
            rs0 += __shfl_xor_sync(FULL, rs0, 2);
            rs1 += __shfl_xor_sync(FULL, rs1, 1);
            rs1 += __shfl_xor_sync(FULL, rs1, 2);
            ls[i][0] = ls[i][0] * corr[i][0] + rs0;
            ls[i][1] = ls[i][1] * corr[i][1] + rs1;

#pragma unroll
            for (int n = 0; n < 9; n++) {
                o[i][n][0] *= corr[i][0]; o[i][n][1] *= corr[i][0];
                o[i][n][2] *= corr[i][1]; o[i][n][3] *= corr[i][1];
            }
        }

        // --- O += P @ V  (shuffle-free: P c-frag is the a-frag under sigma) ---
#pragma unroll
        for (int kk = 0; kk < 4; kk++) {
#pragma unroll
            for (int nn = 0; nn < 9; nn++) {
                uint2 vv = *(const uint2*)(Vb + (nn * 8 + g) * VTST + kk * 8 + 2 * t);
                mma_tf32_pv(o[0][nn], s[0][kk], vv.x, vv.y);
                mma_tf32_pv(o[1][nn], s[1][kk], vv.x, vv.y);
            }
        }
    }

    // epilogue: store attn as tf32 BITS (consumed by out-proj GEMM A)
#pragma unroll
    for (int i = 0; i < 2; i++) {
        float inv0 = 1.f / ls[i][0], inv1 = 1.f / ls[i][1];
        uint32_t* ob = (uint32_t*)attn_out + (long)(q0 + w * 32 + i * 16) * DIMC + h * DH;
#pragma unroll
        for (int nn = 0; nn < 9; nn++) {
            *(uint2*)(ob + (long)g * DIMC + nn * 8 + 2 * t) =
                make_uint2(f2tf32(o[i][nn][0] * inv0), f2tf32(o[i][nn][1] * inv0));
            *(uint2*)(ob + (long)(g + 8) * DIMC + nn * 8 + 2 * t) =
                make_uint2(f2tf32(o[i][nn][2] * inv1), f2tf32(o[i][nn][3] * inv1));
        }
    }
}

// ---------------------------------------------------------------------------
extern "C" void kernel_launch(void* const* d_in, const int* in_sizes, int n_in,
                              void* d_out, int out_size)
{
    const float* fea    = (const float*)d_in[0];
    const float* w_qkv  = (const float*)d_in[1];
    const float* b_qkv  = (const float*)d_in[2];
    const float* w_out  = (const float*)d_in[3];
    const float* b_out  = (const float*)d_in[4];
    const float* conv_w = (const float*)d_in[5];
    float* out = (float*)d_out;

    float* x     = nullptr; cudaGetSymbolAddress((void**)&x,     g_x);
    float* xt    = nullptr; cudaGetSymbolAddress((void**)&xt,    g_xt);
    float* qkv   = nullptr; cudaGetSymbolAddress((void**)&qkv,   g_qkv);
    float* vT    = nullptr; cudaGetSymbolAddress((void**)&vT,    g_vT);
    float* attn  = nullptr; cudaGetSymbolAddress((void**)&attn,  g_attn);
    float* x2    = nullptr; cudaGetSymbolAddress((void**)&x2,    g_x2);
    float* wqkvt = nullptr; cudaGetSymbolAddress((void**)&wqkvt, g_wqkv_t);
    float* woutt = nullptr; cudaGetSymbolAddress((void**)&woutt, g_wout_t);
    float* wcnvt = nullptr; cudaGetSymbolAddress((void**)&wcnvt, g_wconv_t);

    // 0) pre-convert weights to tf32 bits
    wconv_kernel<<<(DIMC * QKVD + 255) / 256, 256>>>(w_qkv, (uint32_t*)wqkvt, DIMC * QKVD);
    wconv_kernel<<<(DIMC * DIMC + 255) / 256, 256>>>(w_out, (uint32_t*)woutt, DIMC * DIMC);
    wconv_kernel<<<(OUTC * DIMC + 255) / 256, 256>>>(conv_w, (uint32_t*)wcnvt, OUTC * DIMC);

    // 1) unfold -> fp32 + tf32 bits
    unfold_kernel<<<(L_TOK * DIMC + 255) / 256, 256>>>(fea, x, (uint32_t*)xt);

    // 2) qkv = xt @ wqkv_t + b_qkv  (Q fp32; K d-interleaved bits; V -> vT natural)
    tf32_gemm_pipe<0, true><<<dim3(QKVD / 64, L_TOK / 128), 256>>>(
        xt, wqkvt, b_qkv, nullptr, qkv, vT, L_TOK, QKVD, DIMC);

    // 3) flash attention -> attn (tf32 bits)
    flash_tc_kernel<<<dim3(L_TOK / 128, NHEADS), 128>>>(qkv, vT, attn);

    // 4) x2 = attn @ wout_t + b_out + x  (stored as tf32 bits)
    tf32_gemm_pipe<1, false><<<dim3(DIMC / 64, L_TOK / 128), 256>>>(
        attn, woutt, b_out, x, x2, nullptr, L_TOK, DIMC, DIMC);

    // 5) out[oc,l] = silu( x2 @ wconv_t^T )
    tf32_gemm_final<<<dim3(OUTC / 64, L_TOK / 128), 256>>>(
        x2, wcnvt, out, L_TOK, OUTC, DIMC);
}